// round 14
// baseline (speedup 1.0000x reference)
#include <cuda_runtime.h>
#include <cstdint>

// EdgeDecoder: out[g] = relu(concat(zA[g], zB[g]) @ w1 + b1) @ w2 + b2
// for 3 edge types concatenated [ptnp | nptp | nptnp], E edges each.
//
// sm_103 (no 'a' features) tensor path: mma.sync m16n8k16 fp16, fp32 accum.
// Persistent, 148 CTAs x 256 threads = 4 warp PAIRS. Each pair owns 64 edges;
// each warp computes an N=64 half (M=64 x N=64 per warp).
// R14: software-pipelined A fragments (register double buffer atA/atB) so
// LDS/cvt/LDGSTS issue under the MMA stream instead of serializing with it.

#define E_CNT    500000
#define TOTAL    1500000
#define NTILES   5860            // ceil(TOTAL / 256)
#define NCTAS    148
#define NTHREADS 256

#define ROW_STRIDE 160           // 40 floats per staged row (32 + pad)
#define STG_BYTES  10240         // 64 rows * 160B

// ---- smem layout (bytes) ----
#define SM_B     0               // 65536: B frags [kc(16)][nt(16)][lane] uint2
#define SM_B1    65536           // 512: b1 as float2[64]
#define SM_W2    66048           // 512: w2 as float2[64]
#define SM_RPTR  66560           // 4096: 4 pairs x 64 rows x {p0,p1} (16B)
#define SM_RED   70656           // 2048: 4 pairs x 2 x 64 floats
#define SM_A     72704           // 122880: 4 pairs x 3 x 10240B staging
#define SM_TOTAL 195584

static __device__ __forceinline__ uint32_t s2u(const void* p) {
    uint32_t a;
    asm("{ .reg .u64 t; cvta.to.shared.u64 t, %1; cvt.u32.u64 %0, t; }"
        : "=r"(a) : "l"(p));
    return a;
}
// pack (lo, hi) fp32 -> fp16x2 register (round to nearest even)
static __device__ __forceinline__ uint32_t packh2(float lo, float hi) {
    uint32_t r;
    asm("cvt.rn.f16x2.f32 %0, %1, %2;" : "=r"(r) : "f"(hi), "f"(lo));
    return r;
}
static __device__ __forceinline__ void cp16(uint32_t dst, const void* src) {
    asm volatile("cp.async.cg.shared.global [%0], [%1], 16;"
                 :: "r"(dst), "l"(src) : "memory");
}
#define CP_COMMIT asm volatile("cp.async.commit_group;" ::: "memory")
#define CP_WAIT1  asm volatile("cp.async.wait_group 1;" ::: "memory")
#define CP_WAIT0  asm volatile("cp.async.wait_group 0;" ::: "memory")
#define PAIR_BAR  asm volatile("bar.sync %0, 64;" :: "r"(pair + 1) : "memory")

// D(16x8) += A(16x16,row,f16) * B(16x8,col,f16), fp32 accumulate in place.
#define MMA(d, A0, A1, A2, A3, B)                                        \
    asm volatile(                                                        \
        "mma.sync.aligned.m16n8k16.row.col.f32.f16.f16.f32 "             \
        "{%0,%1,%2,%3}, {%4,%5,%6,%7}, {%8,%9}, {%0,%1,%2,%3};"          \
        : "+f"((d)[0]), "+f"((d)[1]), "+f"((d)[2]), "+f"((d)[3])         \
        : "r"(A0), "r"(A1), "r"(A2), "r"(A3), "r"((B).x), "r"((B).y))

#define BS(kc, nt) Bsm[((kc) * 16 + (nt)) * 32 + lane]

// issue cp.async for one 32-col stage sn (0..7) into pair buffer sn%3.
// 64 threads of the pair each copy 8 rows x 16B.
#define ISSUE_STAGE(sn)                                                    \
    do {                                                                   \
        const int co_ = ((sn) & 3) * 32 + cseg * 4;                        \
        const uint32_t dst_ = a_s + ((sn) % 3) * STG_BYTES;                \
        _Pragma("unroll")                                                  \
        for (int r_ = 0; r_ < 8; r_++) {                                   \
            const int row_ = r_ * 8 + rtp;                                 \
            const ulonglong2 pp_ =                                         \
                *(const ulonglong2*)(rptr_c + row_ * 16);                  \
            const float* p_ = ((sn) >= 4) ? (const float*)pp_.y            \
                                          : (const float*)pp_.x;           \
            cp16(dst_ + row_ * ROW_STRIDE + cseg * 16, p_ + co_);          \
        }                                                                  \
        CP_COMMIT;                                                         \
    } while (0)

// load + convert the 16 A fragment regs for k-chunk kc2 (0/1) of buffer ab
#define LOADFRAG(at, ab, kc2)                                              \
    do {                                                                   \
        _Pragma("unroll")                                                  \
        for (int mf_ = 0; mf_ < 4; mf_++) {                                \
            const char* ap_ = (ab) + (mf_ * 16 + qr) * ROW_STRIDE          \
                                   + ((kc2) * 16 + 2 * qc) * 4;            \
            float2 v0_ = *(const float2*)(ap_);                            \
            float2 v1_ = *(const float2*)(ap_ + 8 * ROW_STRIDE);           \
            float2 v2_ = *(const float2*)(ap_ + 32);                       \
            float2 v3_ = *(const float2*)(ap_ + 8 * ROW_STRIDE + 32);      \
            (at)[mf_ * 4 + 0] = packh2(v0_.x, v0_.y);                      \
            (at)[mf_ * 4 + 1] = packh2(v1_.x, v1_.y);                      \
            (at)[mf_ * 4 + 2] = packh2(v2_.x, v2_.y);                      \
            (at)[mf_ * 4 + 3] = packh2(v3_.x, v3_.y);                      \
        }                                                                  \
    } while (0)

// 32 MMAs: 4 m-frags x 8 n-tiles for k-chunk kcg, B frags rolled
#define MMABLOCK(at, kcg)                                                  \
    do {                                                                   \
        uint2 bA = BS(kcg, wip * 8), bB = BS(kcg, wip * 8 + 1), bC;        \
        _Pragma("unroll")                                                  \
        for (int nt_ = 0; nt_ < 8; nt_++) {                                \
            if (nt_ < 6) bC = BS(kcg, wip * 8 + nt_ + 2);                  \
            MMA(acc[0][nt_], (at)[0],  (at)[1],  (at)[2],  (at)[3],  bA);  \
            MMA(acc[1][nt_], (at)[4],  (at)[5],  (at)[6],  (at)[7],  bA);  \
            MMA(acc[2][nt_], (at)[8],  (at)[9],  (at)[10], (at)[11], bA);  \
            MMA(acc[3][nt_], (at)[12], (at)[13], (at)[14], (at)[15], bA);  \
            bA = bB; bB = bC;                                              \
        }                                                                  \
    } while (0)

__global__ void __launch_bounds__(NTHREADS, 1)
edgedecoder_kernel(const float* __restrict__ zp, const float* __restrict__ zo,
                   const int* __restrict__ e0, const int* __restrict__ e1,
                   const int* __restrict__ e2,
                   const float* __restrict__ w1, const float* __restrict__ b1,
                   const float* __restrict__ w2, const float* __restrict__ b2,
                   float* __restrict__ out) {
    extern __shared__ char smem[];
    uint2* Bst = (uint2*)(smem + SM_B);
    const uint2* Bsm = (const uint2*)(smem + SM_B);
    float2* b1p = (float2*)(smem + SM_B1);
    float2* w2p = (float2*)(smem + SM_W2);

    const int tid  = threadIdx.x;
    const int warp = tid >> 5;
    const int lane = tid & 31;
    const int qr   = lane >> 2;   // group id 0..7
    const int qc   = lane & 3;    // thread-in-group 0..3
    const int pair = warp >> 1;   // 0..3
    const int wip  = warp & 1;    // N-half within pair
    const int tp   = tid & 63;    // thread index within pair
    const int rtp  = tp >> 3;     // staging row-in-group 0..7
    const int cseg = tp & 7;      // staging 16B segment 0..7

    const uint32_t a_s    = s2u(smem) + SM_A + pair * (3 * STG_BYTES);
    char*          a_c    = smem + SM_A + pair * (3 * STG_BYTES);
    char*          rptr_c = smem + SM_RPTR + pair * 1024;
    float*         red    = (float*)(smem + SM_RED + pair * 512);

    // ---- stage B = w1 (256x128 row-major) as fp16 m16n8k16 frag pairs ----
    for (int i = tid; i < 16 * 16 * 32; i += NTHREADS) {
        int li = i & 31, nt = (i >> 5) & 15, kc = i >> 9;
        int k0 = kc * 16 + 2 * (li & 3);
        int n  = nt * 8 + (li >> 2);
        uint2 v;
        v.x = packh2(w1[k0 * 128 + n],       w1[(k0 + 1) * 128 + n]);
        v.y = packh2(w1[(k0 + 8) * 128 + n], w1[(k0 + 9) * 128 + n]);
        Bst[i] = v;
    }
    if (tid < 64) {
        b1p[tid] = ((const float2*)b1)[tid];
        w2p[tid] = ((const float2*)w2)[tid];
    }
    __syncthreads();

    const float b2v = __ldg(b2);

    for (int tile = blockIdx.x; tile < NTILES; tile += NCTAS) {
        const int base = tile * 256 + pair * 64;

        // ---- per-row gather pointers (row = tp, 64 rows per pair) ----
        {
            int g  = base + tp;
            int gg = (g < TOTAL) ? g : (TOTAL - 1);
            const int* ei;
            const float *t0, *t1;
            int e;
            if (gg < E_CNT)          { ei = e0; t0 = zp; t1 = zo; e = gg; }
            else if (gg < 2 * E_CNT) { ei = e1; t0 = zo; t1 = zp; e = gg - E_CNT; }
            else                     { ei = e2; t0 = zo; t1 = zo; e = gg - 2 * E_CNT; }
            ulonglong2 pp;
            pp.x = (unsigned long long)(t0 + (size_t)__ldg(ei + e) * 128);
            pp.y = (unsigned long long)(t1 + (size_t)__ldg(ei + E_CNT + e) * 128);
            *(ulonglong2*)(rptr_c + tp * 16) = pp;
        }
        PAIR_BAR;

        // ---- accumulators: 64 edges x 64 hidden per warp ----
        float acc[4][8][4];
#pragma unroll
        for (int mf = 0; mf < 4; mf++)
#pragma unroll
            for (int nt = 0; nt < 8; nt++)
#pragma unroll
                for (int j = 0; j < 4; j++) acc[mf][nt][j] = 0.f;

        ISSUE_STAGE(0);
        ISSUE_STAGE(1);
        CP_WAIT1;      // stage 0 landed (this warp's half)
        PAIR_BAR;      // both halves landed

        uint32_t atA[16], atB[16];
        LOADFRAG(atA, a_c, 0);

        // ---- 8 stages of 32 K-columns (= 2 fp16 k16-chunks) each ----
        for (int s = 0; s < 8; s++) {
            const char* ab = a_c + (s % 3) * STG_BYTES;
            // prefetch second k-chunk of this stage under the first MMA block
            LOADFRAG(atB, ab, 1);
            MMABLOCK(atA, s * 2);
            // gather for stage s+2 issues under the second MMA block
            if (s < 6) ISSUE_STAGE(s + 2);
            MMABLOCK(atB, s * 2 + 1);
            if (s < 7) {
                if (s < 6) { CP_WAIT1; } else { CP_WAIT0; }
                PAIR_BAR;  // stage s+1 fully landed; buffer (s-1)%3 drained
                LOADFRAG(atA, a_c + ((s + 1) % 3) * STG_BYTES, 0);
            }
        }

        // ---- epilogue: partial dot over this warp's 64 n's ----
        float s4[8];
#pragma unroll
        for (int j = 0; j < 8; j++) s4[j] = 0.f;
#pragma unroll
        for (int nt = 0; nt < 8; nt++) {
            float2 bb = b1p[(wip * 8 + nt) * 4 + qc];
            float2 ww = w2p[(wip * 8 + nt) * 4 + qc];
#pragma unroll
            for (int mf = 0; mf < 4; mf++) {
                float v0 = fmaxf(acc[mf][nt][0] + bb.x, 0.f);
                float v1 = fmaxf(acc[mf][nt][1] + bb.y, 0.f);
                float v2 = fmaxf(acc[mf][nt][2] + bb.x, 0.f);
                float v3 = fmaxf(acc[mf][nt][3] + bb.y, 0.f);
                s4[mf * 2]     = fmaf(v0, ww.x, fmaf(v1, ww.y, s4[mf * 2]));
                s4[mf * 2 + 1] = fmaf(v2, ww.x, fmaf(v3, ww.y, s4[mf * 2 + 1]));
            }
        }
#pragma unroll
        for (int j = 0; j < 8; j++) {
            s4[j] += __shfl_xor_sync(0xffffffffu, s4[j], 1);
            s4[j] += __shfl_xor_sync(0xffffffffu, s4[j], 2);
        }
        if (qc == 0) {
#pragma unroll
            for (int mf = 0; mf < 4; mf++) {
                red[wip * 64 + mf * 16 + qr]     = s4[mf * 2];
                red[wip * 64 + mf * 16 + 8 + qr] = s4[mf * 2 + 1];
            }
        }
        PAIR_BAR;
        if (wip == 0) {
#pragma unroll
            for (int j = 0; j < 2; j++) {
                int e = lane + j * 32;
                int g = base + e;
                if (g < TOTAL) out[g] = red[e] + red[64 + e] + b2v;
            }
        }
    }
}

extern "C" void kernel_launch(void* const* d_in, const int* in_sizes, int n_in,
                              void* d_out, int out_size) {
    (void)in_sizes; (void)n_in; (void)out_size;
    const float* zp    = (const float*)d_in[0];
    const float* zo    = (const float*)d_in[1];
    const int*   ptnp  = (const int*)d_in[2];
    const int*   nptp  = (const int*)d_in[3];
    const int*   nptnp = (const int*)d_in[4];
    const float* w1    = (const float*)d_in[5];
    const float* b1    = (const float*)d_in[6];
    const float* w2    = (const float*)d_in[7];
    const float* b2    = (const float*)d_in[8];
    float* out = (float*)d_out;

    cudaFuncSetAttribute(edgedecoder_kernel,
                         cudaFuncAttributeMaxDynamicSharedMemorySize, SM_TOTAL);
    edgedecoder_kernel<<<NCTAS, NTHREADS, SM_TOTAL>>>(
        zp, zo, ptnp, nptp, nptnp, w1, b1, w2, b2, out);
}